// round 7
// baseline (speedup 1.0000x reference)
#include <cuda_runtime.h>

#define B  32
#define S  617
#define D  10000
#define L  100
#define C  26
#define W  313        // ceil(D/32) real words
#define WP 320        // padded word count

// ---------------- scratch (device globals; pads stay zero forever) ------------------------------
__device__ __align__(16) int      g_idx[B * S];
__device__ __align__(16) unsigned g_idp[S * WP];   // packed id signs    [s][w]
__device__ __align__(16) unsigned g_lvp[L * WP];   // packed level signs [l][w]
__device__ __align__(16) unsigned g_enc[B * WP];   // packed enc (1 -> +1, 0 -> -1)

// ================= kernel 1: pack sign bits; 16 front-batched LDG.128 per warp ==================
// Warp task = 2048 consecutive floats of one row (= 64 packed words).
#define NROWS (S + L)                        // 717
#define RPR   5                              // regions of 2048 floats (5*2048 >= 10000)
#define PREP_WARPS  (NROWS * RPR)            // 3585
#define PREP_XWARPS 617                      // B*S/32
#define PREP_TWARPS (PREP_WARPS + PREP_XWARPS)
#define PREP_BLOCKS ((PREP_TWARPS + 7) / 8)  // 526

__global__ __launch_bounds__(256) void prep_kernel(const float* __restrict__ x,
                                                   const float* __restrict__ idw,
                                                   const float* __restrict__ lvw) {
    const int lane = threadIdx.x & 31;
    const int gw   = blockIdx.x * 8 + (threadIdx.x >> 5);

    if (gw < PREP_WARPS) {
        const int r      = gw / RPR;
        const int region = gw - r * RPR;
        const float* src = (r < S) ? (idw + (size_t)r * D) : (lvw + (size_t)(r - S) * D);
        unsigned*    dst = (r < S) ? (g_idp + r * WP)       : (g_lvp + (r - S) * WP);

        const int qbase = region * 512;                 // float4-quad base

        // 16 independent coalesced LDG.128, front-batched
        float4 v[16];
        #pragma unroll
        for (int k = 0; k < 16; k++) {
            int q = qbase + k * 32 + lane;
            if (q < D / 4) v[k] = *reinterpret_cast<const float4*>(src + 4 * q);
            else           v[k] = make_float4(0.f, 0.f, 0.f, 0.f);
        }

        // 16 independent shfl pack trees: lane 8g holds word region*64 + 4k + g
        unsigned nib[16];
        #pragma unroll
        for (int k = 0; k < 16; k++) {
            unsigned n = (v[k].x > 0.f ? 1u : 0u) | (v[k].y > 0.f ? 2u : 0u)
                       | (v[k].z > 0.f ? 4u : 0u) | (v[k].w > 0.f ? 8u : 0u);
            n |= __shfl_down_sync(0xffffffffu, n, 1) << 4;
            n |= __shfl_down_sync(0xffffffffu, n, 2) << 8;
            n |= __shfl_down_sync(0xffffffffu, n, 4) << 16;
            nib[k] = n;
        }

        if ((lane & 7) == 0) {
            const int g = lane >> 3;
            #pragma unroll
            for (int k = 0; k < 16; k++) {
                int w = region * 64 + 4 * k + g;
                if (w < W) dst[w] = nib[k];
            }
        }
    } else {
        int e = (gw - PREP_WARPS) * 32 + lane;          // B*S = 19744 = 617*32 exactly
        if (e < B * S) {
            int qv = (int)rintf(x[e] * (float)(L - 1)); // round-half-even == jnp.round
            g_idx[e] = min(max(qv, 0), L - 1);
        }
    }
}

// ================= 6-sample bitplane compressor (26 LOP3 per 6 samples) =========================
__device__ __forceinline__ void csa6(const unsigned xx[6], unsigned p[7]) {
    unsigned t01 = xx[0] ^ xx[1];
    unsigned l1  = t01 ^ xx[2];
    unsigned h1  = (xx[0] & xx[1]) | (xx[2] & t01);
    unsigned t34 = xx[3] ^ xx[4];
    unsigned l2  = t34 ^ xx[5];
    unsigned h2  = (xx[3] & xx[4]) | (xx[5] & t34);
    unsigned tl = l1 ^ l2;
    unsigned c0 = (l1 & l2) | (p[0] & tl);
    p[0] ^= tl;
    unsigned th  = h1 ^ h2;
    unsigned c1a = (h1 & h2) | (p[1] & th);
    unsigned s1  = p[1] ^ th;
    unsigned c1b = s1 & c0;
    p[1] = s1 ^ c0;
    unsigned tc = c1a ^ c1b;
    unsigned c2 = (c1a & c1b) | (p[2] & tc);
    p[2] ^= tc;
    unsigned t;
    t = p[3] & c2; p[3] ^= c2; c2 = t;
    t = p[4] & c2; p[4] ^= c2; c2 = t;
    t = p[5] & c2; p[5] ^= c2; c2 = t;
    p[6] ^= c2;
}

// ================= bit-sliced compare cnt < 309 (309 = 0b0100110101) ===========================
__device__ __forceinline__ unsigned cmp309(const unsigned A[10]) {
    unsigned lt = 0u, eq = 0xffffffffu;
    eq &= ~A[9];
    lt |= eq & ~A[8]; eq &= A[8];
    eq &= ~A[7];
    eq &= ~A[6];
    lt |= eq & ~A[5]; eq &= A[5];
    lt |= eq & ~A[4]; eq &= A[4];
    eq &= ~A[3];
    lt |= eq & ~A[2]; eq &= A[2];
    eq &= ~A[1];
    lt |= eq & ~A[0];
    return lt;
}

// ================= kernel 2 (fused): bind + count + merge -> g_enc, uint2 per thread ============
// grid (B, 5), 320 threads = 10 sample-group warps; each thread owns 2 words (uint2).
__global__ __launch_bounds__(320) void main_kernel() {
    const int b    = blockIdx.x;
    const int wg   = blockIdx.y;            // 0..4, 64-word group
    const int sg   = threadIdx.x >> 5;      // 0..9 sample group
    const int lane = threadIdx.x & 31;
    const int w0   = wg * 64 + lane * 2;    // even word index

    __shared__ __align__(16) unsigned pl[10 * 7 * 64];  // [sg][plane][64 words]
    __shared__ __align__(16) int      sidx[624];         // padded S

    for (int s = threadIdx.x; s < S; s += 320) sidx[s] = g_idx[b * S + s];
    __syncthreads();

    const int s0 = sg * 62;
    const int sn = (sg == 9) ? 59 : 62;     // 9*62 + 59 = 617

    unsigned pA[7] = {0,0,0,0,0,0,0};
    unsigned pB[7] = {0,0,0,0,0,0,0};

    const int full6 = sn / 6;               // 10 or 9
    for (int g = 0; g < full6; g++) {
        unsigned xa[6], xb[6];
        #pragma unroll
        for (int k = 0; k < 6; k++) {
            int s = s0 + g * 6 + k;
            uint2 a = *reinterpret_cast<const uint2*>(g_idp + s * WP + w0);
            uint2 l = *reinterpret_cast<const uint2*>(g_lvp + sidx[s] * WP + w0);
            xa[k] = a.x ^ l.x;
            xb[k] = a.y ^ l.y;
        }
        csa6(xa, pA);
        csa6(xb, pB);
    }
    for (int s = s0 + full6 * 6; s < s0 + sn; s++) {   // remainder 2 or 5 samples
        uint2 a = *reinterpret_cast<const uint2*>(g_idp + s * WP + w0);
        uint2 l = *reinterpret_cast<const uint2*>(g_lvp + sidx[s] * WP + w0);
        unsigned cA = a.x ^ l.x, cB = a.y ^ l.y;
        #pragma unroll
        for (int k = 0; k < 7; k++) {
            unsigned t = pA[k] & cA; pA[k] ^= cA; cA = t;
            t = pB[k] & cB; pB[k] ^= cB; cB = t;
        }
    }

    #pragma unroll
    for (int k = 0; k < 7; k++) {
        uint2 v; v.x = pA[k]; v.y = pB[k];
        *reinterpret_cast<uint2*>(&pl[(sg * 7 + k) * 64 + lane * 2]) = v;
    }
    __syncthreads();

    if (threadIdx.x < 32) {
        unsigned A[10], Bv[10];
        #pragma unroll
        for (int k = 0; k < 10; k++) { A[k] = 0u; Bv[k] = 0u; }
        #pragma unroll
        for (int g2 = 0; g2 < 10; g2++) {
            unsigned cA = 0u, cB = 0u;
            #pragma unroll
            for (int k = 0; k < 7; k++) {
                uint2 q = *reinterpret_cast<const uint2*>(&pl[(g2 * 7 + k) * 64 + lane * 2]);
                unsigned sA = A[k] ^ q.x ^ cA;
                cA = (A[k] & q.x) | (cA & (A[k] ^ q.x));
                A[k] = sA;
                unsigned sB = Bv[k] ^ q.y ^ cB;
                cB = (Bv[k] & q.y) | (cB & (Bv[k] ^ q.y));
                Bv[k] = sB;
            }
            #pragma unroll
            for (int k = 7; k < 10; k++) {
                unsigned t = A[k] & cA;  A[k] ^= cA;  cA = t;
                t = Bv[k] & cB; Bv[k] ^= cB; cB = t;
            }
        }
        uint2 v; v.x = cmp309(A); v.y = cmp309(Bv);
        *reinterpret_cast<uint2*>(g_enc + b * WP + w0) = v;
    }
}

// ================= kernel 3: logits, float4 cw + front-batched loads ============================
// grid (C, 8), 320 threads, 4 batches/block. Thread handles quads qq = k*320+tid (k<7) + tail.
// word = qq>>3 (uniform per 8 lanes -> LDS broadcast), bitbase = (tid&7)*4.
__global__ __launch_bounds__(320) void logits_kernel(const float* __restrict__ cw,
                                                     float* __restrict__ out) {
    const int c    = blockIdx.x;
    const int b0   = blockIdx.y * 4;
    const int tid  = threadIdx.x;
    const int lane = tid & 31;
    const int wrp  = tid >> 5;
    const int bb   = (tid & 7) * 4;         // bit base within word

    __shared__ __align__(16) uint4 se4[WP];
    {
        uint4 v;
        v.x = g_enc[(b0 + 0) * WP + tid];
        v.y = g_enc[(b0 + 1) * WP + tid];
        v.z = g_enc[(b0 + 2) * WP + tid];
        v.w = g_enc[(b0 + 3) * WP + tid];
        se4[tid] = v;
    }
    __syncthreads();

    const float4* cw4 = reinterpret_cast<const float4*>(cw + (size_t)c * D);
    const unsigned MSB = 0x80000000u;

    // front-batched loads (7 full iterations: 7*320 = 2240 quads)
    float4 cv[7];
    uint4  ev[7];
    #pragma unroll
    for (int k = 0; k < 7; k++) cv[k] = __ldg(cw4 + k * 320 + tid);
    #pragma unroll
    for (int k = 0; k < 7; k++) ev[k] = se4[k * 40 + (tid >> 3)];

    float a0 = 0.f, a1 = 0.f, a2 = 0.f, a3 = 0.f;

    #pragma unroll
    for (int k = 0; k < 7; k++) {
        const float* cf = &cv[k].x;
        #pragma unroll
        for (int j = 0; j < 4; j++) {
            unsigned cb = __float_as_uint(cf[j]);
            int sh = 31 - bb - j;
            a0 += __uint_as_float(cb ^ (~(ev[k].x << sh) & MSB));
            a1 += __uint_as_float(cb ^ (~(ev[k].y << sh) & MSB));
            a2 += __uint_as_float(cb ^ (~(ev[k].z << sh) & MSB));
            a3 += __uint_as_float(cb ^ (~(ev[k].w << sh) & MSB));
        }
    }
    if (tid < 260) {                         // tail quads 2240..2499
        float4 cv7 = __ldg(cw4 + 2240 + tid);
        uint4  ev7 = se4[280 + (tid >> 3)];
        const float* cf = &cv7.x;
        #pragma unroll
        for (int j = 0; j < 4; j++) {
            unsigned cb = __float_as_uint(cf[j]);
            int sh = 31 - bb - j;
            a0 += __uint_as_float(cb ^ (~(ev7.x << sh) & MSB));
            a1 += __uint_as_float(cb ^ (~(ev7.y << sh) & MSB));
            a2 += __uint_as_float(cb ^ (~(ev7.z << sh) & MSB));
            a3 += __uint_as_float(cb ^ (~(ev7.w << sh) & MSB));
        }
    }

    __shared__ float red[10][4];
    float a[4] = {a0, a1, a2, a3};
    #pragma unroll
    for (int i = 0; i < 4; i++) {
        float v = a[i];
        #pragma unroll
        for (int o = 16; o > 0; o >>= 1) v += __shfl_down_sync(0xffffffffu, v, o);
        if (lane == 0) red[wrp][i] = v;
    }
    __syncthreads();
    if (tid < 4) {
        float v = 0.0f;
        #pragma unroll
        for (int k = 0; k < 10; k++) v += red[k][tid];
        out[(b0 + tid) * C + c] = v;
    }
}

// ================= launch =======================================================================
extern "C" void kernel_launch(void* const* d_in, const int* in_sizes, int n_in,
                              void* d_out, int out_size) {
    (void)in_sizes; (void)n_in; (void)out_size;
    const float* x   = (const float*)d_in[0];
    const float* idw = (const float*)d_in[1];
    const float* lvw = (const float*)d_in[2];
    const float* cw  = (const float*)d_in[3];
    float* out = (float*)d_out;

    prep_kernel<<<PREP_BLOCKS, 256>>>(x, idw, lvw);
    main_kernel<<<dim3(B, 5), 320>>>();
    logits_kernel<<<dim3(C, B / 4), 320>>>(cw, out);
}

// round 8
// speedup vs baseline: 1.0015x; 1.0015x over previous
#include <cuda_runtime.h>

#define B  32
#define S  617
#define D  10000
#define L  100
#define C  26
#define W  313        // ceil(D/32) real words
#define WP 320        // padded word count

// ---------------- scratch (device globals; pads stay zero forever) ------------------------------
__device__ __align__(16) int      g_idx[B * S];
__device__ __align__(16) unsigned g_idp[S * WP];   // packed id signs    [s][w]
__device__ __align__(16) unsigned g_lvp[L * WP];   // packed level signs [l][w]
__device__ __align__(16) unsigned g_enc[B * WP];   // packed enc (1 -> +1, 0 -> -1)

// ================= kernel 1: ballot-pack sign bits; strided LDG.32, MLP=16 ======================
// Warp task = 512 consecutive floats of one row -> 16 packed words via 16 ballots.
// lane l loads d = 512t + 32k + l  ->  ballot(v>0) IS word 16t+k (bit index == lane == d offset).
#define NROWS (S + L)                        // 717
#define TPR   20                             // tasks of 512 floats per row (20*512 >= 10000)
#define PREP_WARPS  (NROWS * TPR)            // 14340
#define PREP_XWARPS 617                      // B*S/32
#define PREP_BLOCKS ((PREP_WARPS + PREP_XWARPS + 7) / 8)   // 1870

__global__ __launch_bounds__(256) void prep_kernel(const float* __restrict__ x,
                                                   const float* __restrict__ idw,
                                                   const float* __restrict__ lvw) {
    const int lane = threadIdx.x & 31;
    const int gw   = blockIdx.x * 8 + (threadIdx.x >> 5);

    if (gw < PREP_WARPS) {
        const int r = gw / TPR;
        const int t = gw - r * TPR;
        const float* src = (r < S) ? (idw + (size_t)r * D) : (lvw + (size_t)(r - S) * D);
        unsigned*    dst = (r < S) ? (g_idp + r * WP)       : (g_lvp + (r - S) * WP);

        const int base = t * 512 + lane;
        unsigned wsel = 0u;

        if (t < TPR - 1) {
            // fast path: 16 independent coalesced LDG.32, front-batched
            float v[16];
            #pragma unroll
            for (int k = 0; k < 16; k++) v[k] = __ldg(src + base + 32 * k);
            #pragma unroll
            for (int k = 0; k < 16; k++) {
                unsigned bal = __ballot_sync(0xffffffffu, v[k] > 0.0f);
                if (lane == k) wsel = bal;           // SEL: word k kept in lane k
            }
        } else {
            // tail task: d may exceed D; OOB -> bit 0 (pad words stay zero)
            #pragma unroll
            for (int k = 0; k < 16; k++) {
                int d = base + 32 * k;
                float vv = (d < D) ? __ldg(src + d) : 0.0f;
                unsigned bal = __ballot_sync(0xffffffffu, vv > 0.0f);
                if (lane == k) wsel = bal;
            }
        }

        if (lane < 16) dst[t * 16 + lane] = wsel;    // coalesced 64B store
    } else {
        int e = (gw - PREP_WARPS) * 32 + lane;       // B*S = 19744 = 617*32 exactly
        if (e < B * S) {
            int qv = (int)rintf(x[e] * (float)(L - 1));   // round-half-even == jnp.round
            g_idx[e] = min(max(qv, 0), L - 1);
        }
    }
}

// ================= 6-sample bitplane compressor (26 LOP3 per 6 samples) =========================
__device__ __forceinline__ void csa6(const unsigned xx[6], unsigned p[7]) {
    unsigned t01 = xx[0] ^ xx[1];
    unsigned l1  = t01 ^ xx[2];
    unsigned h1  = (xx[0] & xx[1]) | (xx[2] & t01);
    unsigned t34 = xx[3] ^ xx[4];
    unsigned l2  = t34 ^ xx[5];
    unsigned h2  = (xx[3] & xx[4]) | (xx[5] & t34);
    unsigned tl = l1 ^ l2;
    unsigned c0 = (l1 & l2) | (p[0] & tl);
    p[0] ^= tl;
    unsigned th  = h1 ^ h2;
    unsigned c1a = (h1 & h2) | (p[1] & th);
    unsigned s1  = p[1] ^ th;
    unsigned c1b = s1 & c0;
    p[1] = s1 ^ c0;
    unsigned tc = c1a ^ c1b;
    unsigned c2 = (c1a & c1b) | (p[2] & tc);
    p[2] ^= tc;
    unsigned t;
    t = p[3] & c2; p[3] ^= c2; c2 = t;
    t = p[4] & c2; p[4] ^= c2; c2 = t;
    t = p[5] & c2; p[5] ^= c2; c2 = t;
    p[6] ^= c2;
}

// ================= bit-sliced compare cnt < 309 (309 = 0b0100110101) ===========================
__device__ __forceinline__ unsigned cmp309(const unsigned A[10]) {
    unsigned lt = 0u, eq = 0xffffffffu;
    eq &= ~A[9];
    lt |= eq & ~A[8]; eq &= A[8];
    eq &= ~A[7];
    eq &= ~A[6];
    lt |= eq & ~A[5]; eq &= A[5];
    lt |= eq & ~A[4]; eq &= A[4];
    eq &= ~A[3];
    lt |= eq & ~A[2]; eq &= A[2];
    eq &= ~A[1];
    lt |= eq & ~A[0];
    return lt;
}

// ================= kernel 2 (fused): bind + count + merge -> g_enc, uint2 per thread ============
__global__ __launch_bounds__(320) void main_kernel() {
    const int b    = blockIdx.x;
    const int wg   = blockIdx.y;            // 0..4, 64-word group
    const int sg   = threadIdx.x >> 5;      // 0..9 sample group
    const int lane = threadIdx.x & 31;
    const int w0   = wg * 64 + lane * 2;    // even word index

    __shared__ __align__(16) unsigned pl[10 * 7 * 64];  // [sg][plane][64 words]
    __shared__ __align__(16) int      sidx[624];         // padded S

    for (int s = threadIdx.x; s < S; s += 320) sidx[s] = g_idx[b * S + s];
    __syncthreads();

    const int s0 = sg * 62;
    const int sn = (sg == 9) ? 59 : 62;     // 9*62 + 59 = 617

    unsigned pA[7] = {0,0,0,0,0,0,0};
    unsigned pB[7] = {0,0,0,0,0,0,0};

    const int full6 = sn / 6;               // 10 or 9
    for (int g = 0; g < full6; g++) {
        unsigned xa[6], xb[6];
        #pragma unroll
        for (int k = 0; k < 6; k++) {
            int s = s0 + g * 6 + k;
            uint2 a = *reinterpret_cast<const uint2*>(g_idp + s * WP + w0);
            uint2 l = *reinterpret_cast<const uint2*>(g_lvp + sidx[s] * WP + w0);
            xa[k] = a.x ^ l.x;
            xb[k] = a.y ^ l.y;
        }
        csa6(xa, pA);
        csa6(xb, pB);
    }
    for (int s = s0 + full6 * 6; s < s0 + sn; s++) {   // remainder 2 or 5 samples
        uint2 a = *reinterpret_cast<const uint2*>(g_idp + s * WP + w0);
        uint2 l = *reinterpret_cast<const uint2*>(g_lvp + sidx[s] * WP + w0);
        unsigned cA = a.x ^ l.x, cB = a.y ^ l.y;
        #pragma unroll
        for (int k = 0; k < 7; k++) {
            unsigned t = pA[k] & cA; pA[k] ^= cA; cA = t;
            t = pB[k] & cB; pB[k] ^= cB; cB = t;
        }
    }

    #pragma unroll
    for (int k = 0; k < 7; k++) {
        uint2 v; v.x = pA[k]; v.y = pB[k];
        *reinterpret_cast<uint2*>(&pl[(sg * 7 + k) * 64 + lane * 2]) = v;
    }
    __syncthreads();

    if (threadIdx.x < 32) {
        unsigned A[10], Bv[10];
        #pragma unroll
        for (int k = 0; k < 10; k++) { A[k] = 0u; Bv[k] = 0u; }
        #pragma unroll
        for (int g2 = 0; g2 < 10; g2++) {
            unsigned cA = 0u, cB = 0u;
            #pragma unroll
            for (int k = 0; k < 7; k++) {
                uint2 q = *reinterpret_cast<const uint2*>(&pl[(g2 * 7 + k) * 64 + lane * 2]);
                unsigned sA = A[k] ^ q.x ^ cA;
                cA = (A[k] & q.x) | (cA & (A[k] ^ q.x));
                A[k] = sA;
                unsigned sB = Bv[k] ^ q.y ^ cB;
                cB = (Bv[k] & q.y) | (cB & (Bv[k] ^ q.y));
                Bv[k] = sB;
            }
            #pragma unroll
            for (int k = 7; k < 10; k++) {
                unsigned t = A[k] & cA;  A[k] ^= cA;  cA = t;
                t = Bv[k] & cB; Bv[k] ^= cB; cB = t;
            }
        }
        uint2 v; v.x = cmp309(A); v.y = cmp309(Bv);
        *reinterpret_cast<uint2*>(g_enc + b * WP + w0) = v;
    }
}

// ================= kernel 3: logits, float4 cw + front-batched loads ============================
__global__ __launch_bounds__(320) void logits_kernel(const float* __restrict__ cw,
                                                     float* __restrict__ out) {
    const int c    = blockIdx.x;
    const int b0   = blockIdx.y * 4;
    const int tid  = threadIdx.x;
    const int lane = tid & 31;
    const int wrp  = tid >> 5;
    const int bb   = (tid & 7) * 4;         // bit base within word

    __shared__ __align__(16) uint4 se4[WP];
    {
        uint4 v;
        v.x = g_enc[(b0 + 0) * WP + tid];
        v.y = g_enc[(b0 + 1) * WP + tid];
        v.z = g_enc[(b0 + 2) * WP + tid];
        v.w = g_enc[(b0 + 3) * WP + tid];
        se4[tid] = v;
    }
    __syncthreads();

    const float4* cw4 = reinterpret_cast<const float4*>(cw + (size_t)c * D);
    const unsigned MSB = 0x80000000u;

    float4 cv[7];
    uint4  ev[7];
    #pragma unroll
    for (int k = 0; k < 7; k++) cv[k] = __ldg(cw4 + k * 320 + tid);
    #pragma unroll
    for (int k = 0; k < 7; k++) ev[k] = se4[k * 40 + (tid >> 3)];

    float a0 = 0.f, a1 = 0.f, a2 = 0.f, a3 = 0.f;

    #pragma unroll
    for (int k = 0; k < 7; k++) {
        const float* cf = &cv[k].x;
        #pragma unroll
        for (int j = 0; j < 4; j++) {
            unsigned cb = __float_as_uint(cf[j]);
            int sh = 31 - bb - j;
            a0 += __uint_as_float(cb ^ (~(ev[k].x << sh) & MSB));
            a1 += __uint_as_float(cb ^ (~(ev[k].y << sh) & MSB));
            a2 += __uint_as_float(cb ^ (~(ev[k].z << sh) & MSB));
            a3 += __uint_as_float(cb ^ (~(ev[k].w << sh) & MSB));
        }
    }
    if (tid < 260) {                         // tail quads 2240..2499
        float4 cv7 = __ldg(cw4 + 2240 + tid);
        uint4  ev7 = se4[280 + (tid >> 3)];
        const float* cf = &cv7.x;
        #pragma unroll
        for (int j = 0; j < 4; j++) {
            unsigned cb = __float_as_uint(cf[j]);
            int sh = 31 - bb - j;
            a0 += __uint_as_float(cb ^ (~(ev7.x << sh) & MSB));
            a1 += __uint_as_float(cb ^ (~(ev7.y << sh) & MSB));
            a2 += __uint_as_float(cb ^ (~(ev7.z << sh) & MSB));
            a3 += __uint_as_float(cb ^ (~(ev7.w << sh) & MSB));
        }
    }

    __shared__ float red[10][4];
    float a[4] = {a0, a1, a2, a3};
    #pragma unroll
    for (int i = 0; i < 4; i++) {
        float v = a[i];
        #pragma unroll
        for (int o = 16; o > 0; o >>= 1) v += __shfl_down_sync(0xffffffffu, v, o);
        if (lane == 0) red[wrp][i] = v;
    }
    __syncthreads();
    if (tid < 4) {
        float v = 0.0f;
        #pragma unroll
        for (int k = 0; k < 10; k++) v += red[k][tid];
        out[(b0 + tid) * C + c] = v;
    }
}

// ================= launch =======================================================================
extern "C" void kernel_launch(void* const* d_in, const int* in_sizes, int n_in,
                              void* d_out, int out_size) {
    (void)in_sizes; (void)n_in; (void)out_size;
    const float* x   = (const float*)d_in[0];
    const float* idw = (const float*)d_in[1];
    const float* lvw = (const float*)d_in[2];
    const float* cw  = (const float*)d_in[3];
    float* out = (float*)d_out;

    prep_kernel<<<PREP_BLOCKS, 256>>>(x, idw, lvw);
    main_kernel<<<dim3(B, 5), 320>>>();
    logits_kernel<<<dim3(C, B / 4), 320>>>(cw, out);
}